// round 12
// baseline (speedup 1.0000x reference)
#include <cuda_runtime.h>
#include <cuda_fp16.h>
#include <cstdint>
#include <math.h>

// Problem constants
#define R_ROWS  16384   // N*C
#define SPATIAL 1024    // H*W
#define MDIM    512     // mem_dim
#define HIDDIM  512     // spatial/2

// d_out section offsets (floats)
#define OFF_OUTPUT   ((size_t)0)
#define OFF_ATTSP    ((size_t)16777216)
#define OFF_INFLAT   ((size_t)33554432)
#define OFF_MEMNORM  ((size_t)50331648)
#define OFF_ATT      ((size_t)50855936)

// Device scratch (allocation-free)
__device__ float  g_h[MDIM * HIDDIM];
__device__ float  g_memproc[MDIM * SPATIAL];
__device__ float  g_invnorm[R_ROWS];
__device__ __half g_xh[(size_t)R_ROWS * SPATIAL];    // fp16 x
__device__ __half g_mnh[MDIM * SPATIAL];             // fp16 memory_norm
__device__ __half g_mnTh[SPATIAL * MDIM];            // fp16 memory_norm^T
__device__ __half g_atth[(size_t)R_ROWS * MDIM];     // fp16 logits -> fp16 att

// ============================================================================
// mma.sync helpers (sm_80+ — base compute_103 target safe)
// ============================================================================
__device__ __forceinline__ void mma8_tf32(float* c, uint32_t a0, uint32_t a1,
                                          uint32_t a2, uint32_t a3,
                                          uint32_t b0, uint32_t b1) {
    asm volatile(
        "mma.sync.aligned.m16n8k8.row.col.f32.tf32.tf32.f32 "
        "{%0,%1,%2,%3}, {%4,%5,%6,%7}, {%8,%9}, {%0,%1,%2,%3};"
        : "+f"(c[0]), "+f"(c[1]), "+f"(c[2]), "+f"(c[3])
        : "r"(a0), "r"(a1), "r"(a2), "r"(a3), "r"(b0), "r"(b1));
}

__device__ __forceinline__ void mma16_f16(float* c, uint32_t a0, uint32_t a1,
                                          uint32_t a2, uint32_t a3,
                                          uint32_t b0, uint32_t b1) {
    asm volatile(
        "mma.sync.aligned.m16n8k16.row.col.f32.f16.f16.f32 "
        "{%0,%1,%2,%3}, {%4,%5,%6,%7}, {%8,%9}, {%0,%1,%2,%3};"
        : "+f"(c[0]), "+f"(c[1]), "+f"(c[2]), "+f"(c[3])
        : "r"(a0), "r"(a1), "r"(a2), "r"(a3), "r"(b0), "r"(b1));
}

__device__ __forceinline__ void ldmx4(uint32_t& r0, uint32_t& r1,
                                      uint32_t& r2, uint32_t& r3, uint32_t addr) {
    asm volatile("ldmatrix.sync.aligned.m8n8.x4.shared.b16 {%0,%1,%2,%3}, [%4];"
                 : "=r"(r0), "=r"(r1), "=r"(r2), "=r"(r3) : "r"(addr));
}

__device__ __forceinline__ uint32_t tf32_hi(float x) {
    uint32_t h;
    asm("cvt.rna.tf32.f32 %0, %1;" : "=r"(h) : "f"(x));
    return h;
}

__device__ __forceinline__ void cp16(uint32_t dst, const void* src) {
    asm volatile("cp.async.cg.shared.global [%0], [%1], 16;" :: "r"(dst), "l"(src));
}

__device__ __forceinline__ uint32_t pack_half2(float a, float b) {
    __half2 h = __floats2half2_rn(a, b);
    return *reinterpret_cast<uint32_t*>(&h);
}

__device__ __forceinline__ float warp_sum(float v) {
#pragma unroll
    for (int o = 16; o > 0; o >>= 1) v += __shfl_xor_sync(0xffffffffu, v, o);
    return v;
}
__device__ __forceinline__ float warp_max(float v) {
#pragma unroll
    for (int o = 16; o > 0; o >>= 1) v = fmaxf(v, __shfl_xor_sync(0xffffffffu, v, o));
    return v;
}

// ============================================================================
// tf32 NT GEMM tile (device fn) — precision-critical MLP path.
// CTA tile 128x128xBK32, 8 warps, 3-stage cp.async.
// ============================================================================
#define SSTRIDE 36
#define TILEF   (128 * SSTRIDE)
#define STAGEF  (2 * TILEF)
#define GEMM_SMEM_BYTES (3 * STAGEF * 4)

__device__ void mlp_tile(
    int Ntot, int K,
    const float* __restrict__ A, const float* __restrict__ B,
    float* __restrict__ C, const float* __restrict__ bias,
    int bm, int bn)
{
    extern __shared__ float smf[];
    const uint32_t sbase = (uint32_t)__cvta_generic_to_shared(smf);
    const int tid  = threadIdx.x;
    const int wid  = tid >> 5;
    const int lane = tid & 31;
    const int wm   = wid & 1;
    const int wn   = wid >> 1;
    const int tr   = lane >> 2;
    const int tc   = lane & 3;

    const float* At = A + (size_t)bm * K;
    const float* Bt = B + (size_t)bn * K;
    const int nk = K >> 5;

    auto load_stage = [&](int st, int kc) {
        const uint32_t so = sbase + (uint32_t)(st * STAGEF * 4);
#pragma unroll
        for (int i = 0; i < 4; i++) {
            int u = tid + i * 256;
            int row = u >> 3;
            int seg = (u & 7) * 4;
            cp16(so + (uint32_t)((row * SSTRIDE + seg) * 4),
                 At + (size_t)row * K + kc * 32 + seg);
            cp16(so + (uint32_t)((TILEF + row * SSTRIDE + seg) * 4),
                 Bt + (size_t)row * K + kc * 32 + seg);
        }
        asm volatile("cp.async.commit_group;" ::: "memory");
    };

    float c[4][4][4];
#pragma unroll
    for (int mf = 0; mf < 4; mf++)
#pragma unroll
        for (int nf = 0; nf < 4; nf++)
#pragma unroll
            for (int q = 0; q < 4; q++) c[mf][nf][q] = 0.0f;

    load_stage(0, 0);
    load_stage(1, 1);

    for (int s = 0; s < nk; ++s) {
        if (s + 1 < nk) asm volatile("cp.async.wait_group 1;" ::: "memory");
        else            asm volatile("cp.async.wait_group 0;" ::: "memory");
        __syncthreads();
        if (s + 2 < nk) load_stage((s + 2) % 3, s + 2);

        const float* As = smf + (s % 3) * STAGEF;
        const float* Bs = As + TILEF;

#pragma unroll
        for (int kk = 0; kk < 4; kk++) {
            const int kb = kk * 8;
            uint32_t ah[4][4], bh[4][2];
#pragma unroll
            for (int mf = 0; mf < 4; mf++) {
                const int r0 = wm * 64 + mf * 16 + tr;
                ah[mf][0] = tf32_hi(As[r0 * SSTRIDE + kb + tc]);
                ah[mf][1] = tf32_hi(As[(r0 + 8) * SSTRIDE + kb + tc]);
                ah[mf][2] = tf32_hi(As[r0 * SSTRIDE + kb + tc + 4]);
                ah[mf][3] = tf32_hi(As[(r0 + 8) * SSTRIDE + kb + tc + 4]);
            }
#pragma unroll
            for (int nf = 0; nf < 4; nf++) {
                const int n0 = wn * 32 + nf * 8 + tr;
                bh[nf][0] = tf32_hi(Bs[n0 * SSTRIDE + kb + tc]);
                bh[nf][1] = tf32_hi(Bs[n0 * SSTRIDE + kb + tc + 4]);
            }
#pragma unroll
            for (int mf = 0; mf < 4; mf++)
#pragma unroll
                for (int nf = 0; nf < 4; nf++)
                    mma8_tf32(c[mf][nf], ah[mf][0], ah[mf][1], ah[mf][2], ah[mf][3],
                              bh[nf][0], bh[nf][1]);
        }
    }

#pragma unroll
    for (int mf = 0; mf < 4; mf++) {
        const int r0g = bm + wm * 64 + mf * 16 + tr;
#pragma unroll
        for (int nf = 0; nf < 4; nf++) {
            const int cg = bn + wn * 32 + nf * 8 + 2 * tc;
            float bb0 = bias[cg], bb1 = bias[cg + 1];
            float v0 = fmaxf(c[mf][nf][0] + bb0, 0.0f);
            float v1 = fmaxf(c[mf][nf][1] + bb1, 0.0f);
            float v2 = fmaxf(c[mf][nf][2] + bb0, 0.0f);
            float v3 = fmaxf(c[mf][nf][3] + bb1, 0.0f);
            *(float2*)&C[(size_t)r0g * Ntot + cg]       = make_float2(v0, v1);
            *(float2*)&C[(size_t)(r0g + 8) * Ntot + cg] = make_float2(v2, v3);
        }
    }
}

// ============================================================================
// fp16 NT GEMM tile: 4-stage pipeline, 2 CTAs/SM.
// FP16OUT=false: f32 store to C. FP16OUT=true: fp16 (rowscaled) store to Dh.
// ============================================================================
#define SSW      20
#define HTILEW   (128 * SSW)
#define HSTAGEW  (2 * HTILEW)
#define HGEMM_SMEM_BYTES (4 * HSTAGEW * 4)   // 81920 B

template <bool ROWSCALE, bool FP16OUT>
__device__ void gemm16_tile(
    int Ntot, int K,
    const __half* __restrict__ A, const __half* __restrict__ B,
    float* __restrict__ C, __half* __restrict__ Dh,
    const float* __restrict__ rowscale,
    int bm, int bn)
{
    extern __shared__ uint32_t smw[];
    const uint32_t sbase = (uint32_t)__cvta_generic_to_shared(smw);
    const int tid  = threadIdx.x;
    const int wid  = tid >> 5;
    const int lane = tid & 31;
    const int wm   = wid & 1;
    const int wn   = wid >> 1;
    const int tr   = lane >> 2;
    const int tc   = lane & 3;

    const __half* At = A + (size_t)bm * K;
    const __half* Bt = B + (size_t)bn * K;
    const int nk = K >> 5;

    const int q = lane >> 3;
    const int rsub = lane & 7;
    const int arow = wm * 64 + rsub + (q & 1) * 8;
    const int acolw = (q >> 1) * 4;
    const int brow = wn * 32 + rsub + (q >> 1) * 8;
    const int bcolw = (q & 1) * 4;

    auto load_stage = [&](int st, int kc) {
        const uint32_t so = sbase + (uint32_t)(st * HSTAGEW * 4);
#pragma unroll
        for (int i = 0; i < 2; i++) {
            int u = tid + i * 256;
            int row = u >> 2;
            int seg = (u & 3) * 4;
            cp16(so + (uint32_t)((row * SSW + seg) * 4),
                 At + (size_t)row * K + kc * 32 + seg * 2);
            cp16(so + (uint32_t)((HTILEW + row * SSW + seg) * 4),
                 Bt + (size_t)row * K + kc * 32 + seg * 2);
        }
        asm volatile("cp.async.commit_group;" ::: "memory");
    };

    float c[4][4][4];
#pragma unroll
    for (int mf = 0; mf < 4; mf++)
#pragma unroll
        for (int nf = 0; nf < 4; nf++)
#pragma unroll
            for (int qq = 0; qq < 4; qq++) c[mf][nf][qq] = 0.0f;

    load_stage(0, 0);
    load_stage(1, 1);
    load_stage(2, 2);

    for (int s = 0; s < nk; ++s) {
        if (s + 2 < nk)      asm volatile("cp.async.wait_group 2;" ::: "memory");
        else if (s + 1 < nk) asm volatile("cp.async.wait_group 1;" ::: "memory");
        else                 asm volatile("cp.async.wait_group 0;" ::: "memory");
        __syncthreads();
        if (s + 3 < nk) load_stage((s + 3) & 3, s + 3);

        const uint32_t stage = sbase + (uint32_t)((s & 3) * HSTAGEW * 4);
        const uint32_t aAddr0 = stage + (uint32_t)((arow * SSW + acolw) * 4);
        const uint32_t bAddr0 = stage + (uint32_t)((HTILEW + brow * SSW + bcolw) * 4);

#pragma unroll
        for (int kk = 0; kk < 2; kk++) {
            const uint32_t kboff = (uint32_t)(kk * 8 * 4);
            uint32_t a[4][4], b[4][2];
#pragma unroll
            for (int mf = 0; mf < 4; mf++)
                ldmx4(a[mf][0], a[mf][1], a[mf][2], a[mf][3],
                      aAddr0 + kboff + (uint32_t)(mf * 16 * SSW * 4));
#pragma unroll
            for (int nf2 = 0; nf2 < 2; nf2++)
                ldmx4(b[2 * nf2][0], b[2 * nf2][1], b[2 * nf2 + 1][0], b[2 * nf2 + 1][1],
                      bAddr0 + kboff + (uint32_t)(nf2 * 16 * SSW * 4));
#pragma unroll
            for (int mf = 0; mf < 4; mf++)
#pragma unroll
                for (int nf = 0; nf < 4; nf++)
                    mma16_f16(c[mf][nf], a[mf][0], a[mf][1], a[mf][2], a[mf][3],
                              b[nf][0], b[nf][1]);
        }
    }

#pragma unroll
    for (int mf = 0; mf < 4; mf++) {
        const int r0g = bm + wm * 64 + mf * 16 + tr;
        const float rs0 = ROWSCALE ? rowscale[r0g] : 1.0f;
        const float rs1 = ROWSCALE ? rowscale[r0g + 8] : 1.0f;
#pragma unroll
        for (int nf = 0; nf < 4; nf++) {
            const int cg = bn + wn * 32 + nf * 8 + 2 * tc;
            float v0 = c[mf][nf][0], v1 = c[mf][nf][1];
            float v2 = c[mf][nf][2], v3 = c[mf][nf][3];
            if (ROWSCALE) { v0 *= rs0; v1 *= rs0; v2 *= rs1; v3 *= rs1; }
            if (FP16OUT) {
                *(uint32_t*)&Dh[(size_t)r0g * Ntot + cg]       = pack_half2(v0, v1);
                *(uint32_t*)&Dh[(size_t)(r0g + 8) * Ntot + cg] = pack_half2(v2, v3);
            } else {
                *(float2*)&C[(size_t)r0g * Ntot + cg]       = make_float2(v0, v1);
                *(float2*)&C[(size_t)(r0g + 8) * Ntot + cg] = make_float2(v2, v3);
            }
        }
    }
}

// ============================================================================
// softmax + shrink + L1 renorm for 8 rows (one block) from fp16 logits.
// Writes f32 att + fp16 att in place.
// ============================================================================
__device__ void softmax_rows(float* __restrict__ att, int row) {
    const int lane = threadIdx.x & 31;
    uint2*  ph = (uint2*)(g_atth + (size_t)row * MDIM);
    float4* pf = (float4*)(att + (size_t)row * MDIM);
    float f[16];
#pragma unroll
    for (int i = 0; i < 4; i++) {
        uint2 u = ph[lane + 32 * i];
        __half2 h0 = *reinterpret_cast<__half2*>(&u.x);
        __half2 h1 = *reinterpret_cast<__half2*>(&u.y);
        float2 a = __half22float2(h0), bb = __half22float2(h1);
        f[4 * i + 0] = a.x;  f[4 * i + 1] = a.y;
        f[4 * i + 2] = bb.x; f[4 * i + 3] = bb.y;
    }
    float m = -INFINITY;
#pragma unroll
    for (int i = 0; i < 16; i++) m = fmaxf(m, f[i]);
    m = warp_max(m);
    float s = 0.0f;
#pragma unroll
    for (int i = 0; i < 16; i++) { f[i] = expf(f[i] - m); s += f[i]; }
    s = warp_sum(s);
    const float inv = 1.0f / s;
    float t = 0.0f;
#pragma unroll
    for (int i = 0; i < 16; i++) {
        f[i] = fmaxf(f[i] * inv - 0.0025f, 0.0f);
        t += f[i];
    }
    t = warp_sum(t);
    const float inv2 = 1.0f / fmaxf(t, 1e-12f);
#pragma unroll
    for (int i = 0; i < 4; i++) {
        float v0 = f[4 * i + 0] * inv2, v1 = f[4 * i + 1] * inv2;
        float v2 = f[4 * i + 2] * inv2, v3 = f[4 * i + 3] * inv2;
        pf[lane + 32 * i] = make_float4(v0, v1, v2, v3);
        ph[lane + 32 * i] = make_uint2(pack_half2(v0, v1), pack_half2(v2, v3));
    }
}

// ============================================================================
// chanmean + broadcast for one (n, 128-col group) block.
// ============================================================================
__device__ void tail_block(float* __restrict__ attsp, int tb) {
    extern __shared__ float sf[];
    const int n  = tb >> 2;
    const int mg = tb & 3;
    const int t  = threadIdx.x;
    const int m  = t & 127;
    const int ch = t >> 7;
    const __half* base = g_atth + ((size_t)(n * 512 + ch * 256)) * MDIM + mg * 128 + m;
    float s = 0.0f;
#pragma unroll 4
    for (int c = 0; c < 256; c++) s += __half2float(base[(size_t)c * MDIM]);
    sf[t] = s;
    __syncthreads();
    if (t < 128) sf[256 + t] = (sf[t] + sf[t + 128]) * (1.0f / 512.0f);
    __syncthreads();
    float* dst0 = attsp + ((size_t)(n * MDIM + mg * 128)) * SPATIAL;
    for (int m2 = 0; m2 < 128; m2++) {
        const float v = sf[256 + m2];
        ((float4*)(dst0 + (size_t)m2 * SPATIAL))[t] = make_float4(v, v, v, v);
    }
}

// ============================================================================
// Fused input processing: copy x -> input_flat, fp16(x) -> g_xh, invnorm.
// ============================================================================
__device__ void input_rows(const float* __restrict__ x, float* __restrict__ inflat,
                           int gwarp, int nwarps, int base) {
    const int lane = threadIdx.x & 31;
    for (int row = base + gwarp; row < base + 8192; row += nwarps) {
        const float4* p = (const float4*)(x + (size_t)row * SPATIAL);
        float4* of = (float4*)(inflat + (size_t)row * SPATIAL);
        uint2*  xo = (uint2*)(g_xh + (size_t)row * SPATIAL);
        float s = 0.0f;
#pragma unroll
        for (int i = 0; i < 8; i++) {
            float4 v = p[lane + 32 * i];
            s += v.x * v.x + v.y * v.y + v.z * v.z + v.w * v.w;
            of[lane + 32 * i] = v;
            xo[lane + 32 * i] = make_uint2(pack_half2(v.x, v.y), pack_half2(v.z, v.w));
        }
        s = warp_sum(s);
        if (lane == 0) g_invnorm[row] = 1.0f / fmaxf(sqrtf(s), 1e-12f);
    }
}

// K1: MLP1 (16 CTAs) + input rows 0..8191 (132 CTAs)
__global__ void __launch_bounds__(256, 1) k1_mlp1_input(
    const float* __restrict__ memory, const float* __restrict__ w1,
    const float* __restrict__ b1, const float* __restrict__ x,
    float* __restrict__ inflat)
{
    const int b = blockIdx.x;
    if (b < 16) {
        mlp_tile(HIDDIM, SPATIAL, memory, w1, g_h, b1, (b >> 2) * 128, (b & 3) * 128);
    } else {
        const int gwarp = (b - 16) * 8 + (threadIdx.x >> 5);
        input_rows(x, inflat, gwarp, 132 * 8, 0);
    }
}

// K2: MLP2 (32 CTAs) + input rows 8192..16383 (116 CTAs)
__global__ void __launch_bounds__(256, 1) k2_mlp2_input(
    const float* __restrict__ w2, const float* __restrict__ b2,
    const float* __restrict__ x, float* __restrict__ inflat)
{
    const int b = blockIdx.x;
    if (b < 32) {
        mlp_tile(SPATIAL, HIDDIM, g_h, w2, g_memproc, b2, (b >> 3) * 128, (b & 7) * 128);
    } else {
        const int gwarp = (b - 32) * 8 + (threadIdx.x >> 5);
        input_rows(x, inflat, gwarp, 116 * 8, 8192);
    }
}

// ============================================================================
// rownorm + fp16 + transposed fp16 in one pass. Block per row.
// ============================================================================
__global__ __launch_bounds__(256) void rownorm_t_kernel(float* __restrict__ dst) {
    __shared__ float sm[8];
    const int row  = blockIdx.x;
    const int tid  = threadIdx.x;
    const int lane = tid & 31;
    const int w    = tid >> 5;
    const float4* p = (const float4*)(g_memproc + (size_t)row * SPATIAL);
    float4 v = p[tid];
    float s = v.x * v.x + v.y * v.y + v.z * v.z + v.w * v.w;
    s = warp_sum(s);
    if (lane == 0) sm[w] = s;
    __syncthreads();
    float tot = 0.0f;
#pragma unroll
    for (int i = 0; i < 8; i++) tot += sm[i];
    const float sc = 1.0f / fmaxf(sqrtf(tot), 1e-12f);
    float4 o = make_float4(v.x * sc, v.y * sc, v.z * sc, v.w * sc);
    ((float4*)(dst + (size_t)row * SPATIAL))[tid] = o;
    ((uint2*)(g_mnh + (size_t)row * SPATIAL))[tid] =
        make_uint2(pack_half2(o.x, o.y), pack_half2(o.z, o.w));
    g_mnTh[(size_t)(4 * tid + 0) * MDIM + row] = __float2half_rn(o.x);
    g_mnTh[(size_t)(4 * tid + 1) * MDIM + row] = __float2half_rn(o.y);
    g_mnTh[(size_t)(4 * tid + 2) * MDIM + row] = __float2half_rn(o.z);
    g_mnTh[(size_t)(4 * tid + 3) * MDIM + row] = __float2half_rn(o.w);
}

// ============================================================================
// L4: GEMM3 half 1 (rows 0..8191) — 256 tiles = one full wave.
// ============================================================================
__global__ void __launch_bounds__(256, 2) k_g3h1() {
    const int b = blockIdx.x;
    gemm16_tile<true, true>(MDIM, SPATIAL, g_xh, g_mnh, nullptr, g_atth,
                            g_invnorm, (b >> 2) * 128, (b & 3) * 128);
}

// ============================================================================
// L5: GEMM3 half 2 (256 tiles) + softmax half 1 (1024 blocks, rows 0..8191)
// ============================================================================
__global__ void __launch_bounds__(256, 2) k_g3h2_smh1(float* __restrict__ att) {
    const int b = blockIdx.x;
    if (b < 256) {
        gemm16_tile<true, true>(MDIM, SPATIAL, g_xh, g_mnh, nullptr, g_atth,
                                g_invnorm, 8192 + (b >> 2) * 128, (b & 3) * 128);
    } else {
        softmax_rows(att, (b - 256) * 8 + (threadIdx.x >> 5));
    }
}

// ============================================================================
// L6: GEMM4 half 1 (512 tiles, rows 0..8191) + softmax half 2 (1024 blocks)
//     + tail n=0..15 (64 blocks)
// ============================================================================
__global__ void __launch_bounds__(256, 2) k_g4h1_smh2_tailh1(
    float* __restrict__ outp, float* __restrict__ att, float* __restrict__ attsp)
{
    const int b = blockIdx.x;
    if (b < 512) {
        gemm16_tile<false, false>(SPATIAL, MDIM, g_atth, g_mnTh, outp, nullptr,
                                  nullptr, (b >> 3) * 128, (b & 7) * 128);
    } else if (b < 1536) {
        softmax_rows(att, 8192 + (b - 512) * 8 + (threadIdx.x >> 5));
    } else {
        tail_block(attsp, b - 1536);          // tb 0..63 -> n 0..15
    }
}

// ============================================================================
// L7: GEMM4 half 2 (512 tiles, rows 8192..16383) + tail n=16..31 (64 blocks)
// ============================================================================
__global__ void __launch_bounds__(256, 2) k_g4h2_tailh2(
    float* __restrict__ outp, float* __restrict__ attsp)
{
    const int b = blockIdx.x;
    if (b < 512) {
        gemm16_tile<false, false>(SPATIAL, MDIM, g_atth, g_mnTh, outp, nullptr,
                                  nullptr, 8192 + (b >> 3) * 128, (b & 7) * 128);
    } else {
        tail_block(attsp, 64 + (b - 512));    // tb 64..127 -> n 16..31
    }
}

// ============================================================================
extern "C" void kernel_launch(void* const* d_in, const int* in_sizes, int n_in,
                              void* d_out, int out_size) {
    (void)in_sizes; (void)n_in; (void)out_size;
    const float* x      = (const float*)d_in[0];
    const float* memory = (const float*)d_in[1];
    const float* w1     = (const float*)d_in[2];
    const float* b1     = (const float*)d_in[3];
    const float* w2     = (const float*)d_in[4];
    const float* b2     = (const float*)d_in[5];

    float* out = (float*)d_out;
    float* out_output  = out + OFF_OUTPUT;
    float* out_attsp   = out + OFF_ATTSP;
    float* out_inflat  = out + OFF_INFLAT;
    float* out_memnorm = out + OFF_MEMNORM;
    float* out_att     = out + OFF_ATT;

    cudaFuncSetAttribute((const void*)k1_mlp1_input,
                         cudaFuncAttributeMaxDynamicSharedMemorySize, GEMM_SMEM_BYTES);
    cudaFuncSetAttribute((const void*)k2_mlp2_input,
                         cudaFuncAttributeMaxDynamicSharedMemorySize, GEMM_SMEM_BYTES);
    cudaFuncSetAttribute((const void*)k_g3h1,
                         cudaFuncAttributeMaxDynamicSharedMemorySize, HGEMM_SMEM_BYTES);
    cudaFuncSetAttribute((const void*)k_g3h2_smh1,
                         cudaFuncAttributeMaxDynamicSharedMemorySize, HGEMM_SMEM_BYTES);
    cudaFuncSetAttribute((const void*)k_g4h1_smh2_tailh1,
                         cudaFuncAttributeMaxDynamicSharedMemorySize, HGEMM_SMEM_BYTES);
    cudaFuncSetAttribute((const void*)k_g4h2_tailh2,
                         cudaFuncAttributeMaxDynamicSharedMemorySize, HGEMM_SMEM_BYTES);

    // L1: MLP layer 1 || input processing (rows 0..8191)
    k1_mlp1_input<<<148, 256, GEMM_SMEM_BYTES>>>(memory, w1, b1, x, out_inflat);
    // L2: MLP layer 2 || input processing (rows 8192..16383)
    k2_mlp2_input<<<148, 256, GEMM_SMEM_BYTES>>>(w2, b2, x, out_inflat);
    // L3: memory_norm (f32 + fp16 + fp16-transposed)
    rownorm_t_kernel<<<MDIM, 256>>>(out_memnorm);
    // L4: GEMM3 H1
    k_g3h1<<<256, 256, HGEMM_SMEM_BYTES>>>();
    // L5: GEMM3 H2 || softmax H1
    k_g3h2_smh1<<<1280, 256, HGEMM_SMEM_BYTES>>>(out_att);
    // L6: GEMM4 H1 || softmax H2 || tail H1
    k_g4h1_smh2_tailh1<<<1600, 256, HGEMM_SMEM_BYTES>>>(out_output, out_att, out_attsp);
    // L7: GEMM4 H2 || tail H2
    k_g4h2_tailh2<<<576, 256, HGEMM_SMEM_BYTES>>>(out_output, out_attsp);
}

// round 13
// speedup vs baseline: 1.2325x; 1.2325x over previous
#include <cuda_runtime.h>
#include <cuda_fp16.h>
#include <cstdint>
#include <math.h>

// Problem constants
#define R_ROWS  16384   // N*C
#define SPATIAL 1024    // H*W
#define MDIM    512     // mem_dim
#define HIDDIM  512     // spatial/2

// Input-row split between k1 and k2 (rebalanced: MLP1 is ~2x MLP2's work)
#define K1_ROWS 10752
#define K2_ROWS (R_ROWS - K1_ROWS)

// d_out section offsets (floats)
#define OFF_OUTPUT   ((size_t)0)
#define OFF_ATTSP    ((size_t)16777216)
#define OFF_INFLAT   ((size_t)33554432)
#define OFF_MEMNORM  ((size_t)50331648)
#define OFF_ATT      ((size_t)50855936)

// Device scratch (allocation-free)
__device__ float  g_h[MDIM * HIDDIM];
__device__ float  g_memproc[MDIM * SPATIAL];
__device__ float  g_invnorm[R_ROWS];
__device__ __half g_xh[(size_t)R_ROWS * SPATIAL];    // fp16 x
__device__ __half g_mnh[MDIM * SPATIAL];             // fp16 memory_norm
__device__ __half g_mnTh[SPATIAL * MDIM];            // fp16 memory_norm^T
__device__ __half g_atth[(size_t)R_ROWS * MDIM];     // fp16 logits -> fp16 att

// ============================================================================
// mma.sync helpers (sm_80+ — base compute_103 target safe)
// ============================================================================
__device__ __forceinline__ void mma8_tf32(float* c, uint32_t a0, uint32_t a1,
                                          uint32_t a2, uint32_t a3,
                                          uint32_t b0, uint32_t b1) {
    asm volatile(
        "mma.sync.aligned.m16n8k8.row.col.f32.tf32.tf32.f32 "
        "{%0,%1,%2,%3}, {%4,%5,%6,%7}, {%8,%9}, {%0,%1,%2,%3};"
        : "+f"(c[0]), "+f"(c[1]), "+f"(c[2]), "+f"(c[3])
        : "r"(a0), "r"(a1), "r"(a2), "r"(a3), "r"(b0), "r"(b1));
}

__device__ __forceinline__ void mma16_f16(float* c, uint32_t a0, uint32_t a1,
                                          uint32_t a2, uint32_t a3,
                                          uint32_t b0, uint32_t b1) {
    asm volatile(
        "mma.sync.aligned.m16n8k16.row.col.f32.f16.f16.f32 "
        "{%0,%1,%2,%3}, {%4,%5,%6,%7}, {%8,%9}, {%0,%1,%2,%3};"
        : "+f"(c[0]), "+f"(c[1]), "+f"(c[2]), "+f"(c[3])
        : "r"(a0), "r"(a1), "r"(a2), "r"(a3), "r"(b0), "r"(b1));
}

__device__ __forceinline__ void ldmx4(uint32_t& r0, uint32_t& r1,
                                      uint32_t& r2, uint32_t& r3, uint32_t addr) {
    asm volatile("ldmatrix.sync.aligned.m8n8.x4.shared.b16 {%0,%1,%2,%3}, [%4];"
                 : "=r"(r0), "=r"(r1), "=r"(r2), "=r"(r3) : "r"(addr));
}

__device__ __forceinline__ uint32_t tf32_hi(float x) {
    uint32_t h;
    asm("cvt.rna.tf32.f32 %0, %1;" : "=r"(h) : "f"(x));
    return h;
}

__device__ __forceinline__ void cp16(uint32_t dst, const void* src) {
    asm volatile("cp.async.cg.shared.global [%0], [%1], 16;" :: "r"(dst), "l"(src));
}

__device__ __forceinline__ uint32_t pack_half2(float a, float b) {
    __half2 h = __floats2half2_rn(a, b);
    return *reinterpret_cast<uint32_t*>(&h);
}

__device__ __forceinline__ float warp_sum(float v) {
#pragma unroll
    for (int o = 16; o > 0; o >>= 1) v += __shfl_xor_sync(0xffffffffu, v, o);
    return v;
}
__device__ __forceinline__ float warp_max(float v) {
#pragma unroll
    for (int o = 16; o > 0; o >>= 1) v = fmaxf(v, __shfl_xor_sync(0xffffffffu, v, o));
    return v;
}

// ============================================================================
// tf32 NT GEMM tile (device fn) — precision-critical MLP path.
// CTA tile 128x128xBK32, 8 warps, 3-stage cp.async.
// ============================================================================
#define SSTRIDE 36
#define TILEF   (128 * SSTRIDE)
#define STAGEF  (2 * TILEF)
#define GEMM_SMEM_BYTES (3 * STAGEF * 4)

__device__ void mlp_tile(
    int Ntot, int K,
    const float* __restrict__ A, const float* __restrict__ B,
    float* __restrict__ C, const float* __restrict__ bias,
    int bm, int bn)
{
    extern __shared__ float smf[];
    const uint32_t sbase = (uint32_t)__cvta_generic_to_shared(smf);
    const int tid  = threadIdx.x;
    const int wid  = tid >> 5;
    const int lane = tid & 31;
    const int wm   = wid & 1;
    const int wn   = wid >> 1;
    const int tr   = lane >> 2;
    const int tc   = lane & 3;

    const float* At = A + (size_t)bm * K;
    const float* Bt = B + (size_t)bn * K;
    const int nk = K >> 5;

    auto load_stage = [&](int st, int kc) {
        const uint32_t so = sbase + (uint32_t)(st * STAGEF * 4);
#pragma unroll
        for (int i = 0; i < 4; i++) {
            int u = tid + i * 256;
            int row = u >> 3;
            int seg = (u & 7) * 4;
            cp16(so + (uint32_t)((row * SSTRIDE + seg) * 4),
                 At + (size_t)row * K + kc * 32 + seg);
            cp16(so + (uint32_t)((TILEF + row * SSTRIDE + seg) * 4),
                 Bt + (size_t)row * K + kc * 32 + seg);
        }
        asm volatile("cp.async.commit_group;" ::: "memory");
    };

    float c[4][4][4];
#pragma unroll
    for (int mf = 0; mf < 4; mf++)
#pragma unroll
        for (int nf = 0; nf < 4; nf++)
#pragma unroll
            for (int q = 0; q < 4; q++) c[mf][nf][q] = 0.0f;

    load_stage(0, 0);
    load_stage(1, 1);

    for (int s = 0; s < nk; ++s) {
        if (s + 1 < nk) asm volatile("cp.async.wait_group 1;" ::: "memory");
        else            asm volatile("cp.async.wait_group 0;" ::: "memory");
        __syncthreads();
        if (s + 2 < nk) load_stage((s + 2) % 3, s + 2);

        const float* As = smf + (s % 3) * STAGEF;
        const float* Bs = As + TILEF;

#pragma unroll
        for (int kk = 0; kk < 4; kk++) {
            const int kb = kk * 8;
            uint32_t ah[4][4], bh[4][2];
#pragma unroll
            for (int mf = 0; mf < 4; mf++) {
                const int r0 = wm * 64 + mf * 16 + tr;
                ah[mf][0] = tf32_hi(As[r0 * SSTRIDE + kb + tc]);
                ah[mf][1] = tf32_hi(As[(r0 + 8) * SSTRIDE + kb + tc]);
                ah[mf][2] = tf32_hi(As[r0 * SSTRIDE + kb + tc + 4]);
                ah[mf][3] = tf32_hi(As[(r0 + 8) * SSTRIDE + kb + tc + 4]);
            }
#pragma unroll
            for (int nf = 0; nf < 4; nf++) {
                const int n0 = wn * 32 + nf * 8 + tr;
                bh[nf][0] = tf32_hi(Bs[n0 * SSTRIDE + kb + tc]);
                bh[nf][1] = tf32_hi(Bs[n0 * SSTRIDE + kb + tc + 4]);
            }
#pragma unroll
            for (int mf = 0; mf < 4; mf++)
#pragma unroll
                for (int nf = 0; nf < 4; nf++)
                    mma8_tf32(c[mf][nf], ah[mf][0], ah[mf][1], ah[mf][2], ah[mf][3],
                              bh[nf][0], bh[nf][1]);
        }
    }

#pragma unroll
    for (int mf = 0; mf < 4; mf++) {
        const int r0g = bm + wm * 64 + mf * 16 + tr;
#pragma unroll
        for (int nf = 0; nf < 4; nf++) {
            const int cg = bn + wn * 32 + nf * 8 + 2 * tc;
            float bb0 = bias[cg], bb1 = bias[cg + 1];
            float v0 = fmaxf(c[mf][nf][0] + bb0, 0.0f);
            float v1 = fmaxf(c[mf][nf][1] + bb1, 0.0f);
            float v2 = fmaxf(c[mf][nf][2] + bb0, 0.0f);
            float v3 = fmaxf(c[mf][nf][3] + bb1, 0.0f);
            *(float2*)&C[(size_t)r0g * Ntot + cg]       = make_float2(v0, v1);
            *(float2*)&C[(size_t)(r0g + 8) * Ntot + cg] = make_float2(v2, v3);
        }
    }
}

// ============================================================================
// fp16 NT GEMM tile: 4-stage pipeline, 2 CTAs/SM.
// FP16OUT=false: f32 store to C. FP16OUT=true: fp16 (rowscaled) store to Dh.
// ============================================================================
#define SSW      20
#define HTILEW   (128 * SSW)
#define HSTAGEW  (2 * HTILEW)
#define HGEMM_SMEM_BYTES (4 * HSTAGEW * 4)   // 81920 B

template <bool ROWSCALE, bool FP16OUT>
__device__ void gemm16_tile(
    int Ntot, int K,
    const __half* __restrict__ A, const __half* __restrict__ B,
    float* __restrict__ C, __half* __restrict__ Dh,
    const float* __restrict__ rowscale,
    int bm, int bn)
{
    extern __shared__ uint32_t smw[];
    const uint32_t sbase = (uint32_t)__cvta_generic_to_shared(smw);
    const int tid  = threadIdx.x;
    const int wid  = tid >> 5;
    const int lane = tid & 31;
    const int wm   = wid & 1;
    const int wn   = wid >> 1;
    const int tr   = lane >> 2;
    const int tc   = lane & 3;

    const __half* At = A + (size_t)bm * K;
    const __half* Bt = B + (size_t)bn * K;
    const int nk = K >> 5;

    const int q = lane >> 3;
    const int rsub = lane & 7;
    const int arow = wm * 64 + rsub + (q & 1) * 8;
    const int acolw = (q >> 1) * 4;
    const int brow = wn * 32 + rsub + (q >> 1) * 8;
    const int bcolw = (q & 1) * 4;

    auto load_stage = [&](int st, int kc) {
        const uint32_t so = sbase + (uint32_t)(st * HSTAGEW * 4);
#pragma unroll
        for (int i = 0; i < 2; i++) {
            int u = tid + i * 256;
            int row = u >> 2;
            int seg = (u & 3) * 4;
            cp16(so + (uint32_t)((row * SSW + seg) * 4),
                 At + (size_t)row * K + kc * 32 + seg * 2);
            cp16(so + (uint32_t)((HTILEW + row * SSW + seg) * 4),
                 Bt + (size_t)row * K + kc * 32 + seg * 2);
        }
        asm volatile("cp.async.commit_group;" ::: "memory");
    };

    float c[4][4][4];
#pragma unroll
    for (int mf = 0; mf < 4; mf++)
#pragma unroll
        for (int nf = 0; nf < 4; nf++)
#pragma unroll
            for (int qq = 0; qq < 4; qq++) c[mf][nf][qq] = 0.0f;

    load_stage(0, 0);
    load_stage(1, 1);
    load_stage(2, 2);

    for (int s = 0; s < nk; ++s) {
        if (s + 2 < nk)      asm volatile("cp.async.wait_group 2;" ::: "memory");
        else if (s + 1 < nk) asm volatile("cp.async.wait_group 1;" ::: "memory");
        else                 asm volatile("cp.async.wait_group 0;" ::: "memory");
        __syncthreads();
        if (s + 3 < nk) load_stage((s + 3) & 3, s + 3);

        const uint32_t stage = sbase + (uint32_t)((s & 3) * HSTAGEW * 4);
        const uint32_t aAddr0 = stage + (uint32_t)((arow * SSW + acolw) * 4);
        const uint32_t bAddr0 = stage + (uint32_t)((HTILEW + brow * SSW + bcolw) * 4);

#pragma unroll
        for (int kk = 0; kk < 2; kk++) {
            const uint32_t kboff = (uint32_t)(kk * 8 * 4);
            uint32_t a[4][4], b[4][2];
#pragma unroll
            for (int mf = 0; mf < 4; mf++)
                ldmx4(a[mf][0], a[mf][1], a[mf][2], a[mf][3],
                      aAddr0 + kboff + (uint32_t)(mf * 16 * SSW * 4));
#pragma unroll
            for (int nf2 = 0; nf2 < 2; nf2++)
                ldmx4(b[2 * nf2][0], b[2 * nf2][1], b[2 * nf2 + 1][0], b[2 * nf2 + 1][1],
                      bAddr0 + kboff + (uint32_t)(nf2 * 16 * SSW * 4));
#pragma unroll
            for (int mf = 0; mf < 4; mf++)
#pragma unroll
                for (int nf = 0; nf < 4; nf++)
                    mma16_f16(c[mf][nf], a[mf][0], a[mf][1], a[mf][2], a[mf][3],
                              b[nf][0], b[nf][1]);
        }
    }

#pragma unroll
    for (int mf = 0; mf < 4; mf++) {
        const int r0g = bm + wm * 64 + mf * 16 + tr;
        const float rs0 = ROWSCALE ? rowscale[r0g] : 1.0f;
        const float rs1 = ROWSCALE ? rowscale[r0g + 8] : 1.0f;
#pragma unroll
        for (int nf = 0; nf < 4; nf++) {
            const int cg = bn + wn * 32 + nf * 8 + 2 * tc;
            float v0 = c[mf][nf][0], v1 = c[mf][nf][1];
            float v2 = c[mf][nf][2], v3 = c[mf][nf][3];
            if (ROWSCALE) { v0 *= rs0; v1 *= rs0; v2 *= rs1; v3 *= rs1; }
            if (FP16OUT) {
                *(uint32_t*)&Dh[(size_t)r0g * Ntot + cg]       = pack_half2(v0, v1);
                *(uint32_t*)&Dh[(size_t)(r0g + 8) * Ntot + cg] = pack_half2(v2, v3);
            } else {
                *(float2*)&C[(size_t)r0g * Ntot + cg]       = make_float2(v0, v1);
                *(float2*)&C[(size_t)(r0g + 8) * Ntot + cg] = make_float2(v2, v3);
            }
        }
    }
}

// ============================================================================
// Fused input processing: copy x -> input_flat, fp16(x) -> g_xh, invnorm.
// Warp-strided over [base, base+count).
// ============================================================================
__device__ void input_rows(const float* __restrict__ x, float* __restrict__ inflat,
                           int gwarp, int nwarps, int base, int count) {
    const int lane = threadIdx.x & 31;
    for (int row = base + gwarp; row < base + count; row += nwarps) {
        const float4* p = (const float4*)(x + (size_t)row * SPATIAL);
        float4* of = (float4*)(inflat + (size_t)row * SPATIAL);
        uint2*  xo = (uint2*)(g_xh + (size_t)row * SPATIAL);
        float s = 0.0f;
#pragma unroll
        for (int i = 0; i < 8; i++) {
            float4 v = p[lane + 32 * i];
            s += v.x * v.x + v.y * v.y + v.z * v.z + v.w * v.w;
            of[lane + 32 * i] = v;
            xo[lane + 32 * i] = make_uint2(pack_half2(v.x, v.y), pack_half2(v.z, v.w));
        }
        s = warp_sum(s);
        if (lane == 0) g_invnorm[row] = 1.0f / fmaxf(sqrtf(s), 1e-12f);
    }
}

// K1: MLP1 (16 CTAs) + input rows 0..K1_ROWS-1 (132 CTAs)
__global__ void __launch_bounds__(256, 1) k1_mlp1_input(
    const float* __restrict__ memory, const float* __restrict__ w1,
    const float* __restrict__ b1, const float* __restrict__ x,
    float* __restrict__ inflat)
{
    const int b = blockIdx.x;
    if (b < 16) {
        mlp_tile(HIDDIM, SPATIAL, memory, w1, g_h, b1, (b >> 2) * 128, (b & 3) * 128);
    } else {
        const int gwarp = (b - 16) * 8 + (threadIdx.x >> 5);
        input_rows(x, inflat, gwarp, 132 * 8, 0, K1_ROWS);
    }
}

// K2: MLP2 (32 CTAs) + input rows K1_ROWS..16383 (116 CTAs)
__global__ void __launch_bounds__(256, 1) k2_mlp2_input(
    const float* __restrict__ w2, const float* __restrict__ b2,
    const float* __restrict__ x, float* __restrict__ inflat)
{
    const int b = blockIdx.x;
    if (b < 32) {
        mlp_tile(SPATIAL, HIDDIM, g_h, w2, g_memproc, b2, (b >> 3) * 128, (b & 7) * 128);
    } else {
        const int gwarp = (b - 32) * 8 + (threadIdx.x >> 5);
        input_rows(x, inflat, gwarp, 116 * 8, K1_ROWS, K2_ROWS);
    }
}

// ============================================================================
// rownorm + fp16 + transposed fp16 in one pass. Block per row.
// ============================================================================
__global__ __launch_bounds__(256) void rownorm_t_kernel(float* __restrict__ dst) {
    __shared__ float sm[8];
    const int row  = blockIdx.x;
    const int tid  = threadIdx.x;
    const int lane = tid & 31;
    const int w    = tid >> 5;
    const float4* p = (const float4*)(g_memproc + (size_t)row * SPATIAL);
    float4 v = p[tid];
    float s = v.x * v.x + v.y * v.y + v.z * v.z + v.w * v.w;
    s = warp_sum(s);
    if (lane == 0) sm[w] = s;
    __syncthreads();
    float tot = 0.0f;
#pragma unroll
    for (int i = 0; i < 8; i++) tot += sm[i];
    const float sc = 1.0f / fmaxf(sqrtf(tot), 1e-12f);
    float4 o = make_float4(v.x * sc, v.y * sc, v.z * sc, v.w * sc);
    ((float4*)(dst + (size_t)row * SPATIAL))[tid] = o;
    ((uint2*)(g_mnh + (size_t)row * SPATIAL))[tid] =
        make_uint2(pack_half2(o.x, o.y), pack_half2(o.z, o.w));
    g_mnTh[(size_t)(4 * tid + 0) * MDIM + row] = __float2half_rn(o.x);
    g_mnTh[(size_t)(4 * tid + 1) * MDIM + row] = __float2half_rn(o.y);
    g_mnTh[(size_t)(4 * tid + 2) * MDIM + row] = __float2half_rn(o.z);
    g_mnTh[(size_t)(4 * tid + 3) * MDIM + row] = __float2half_rn(o.w);
}

// ============================================================================
// GEMM3: fp16 rowscaled logits -> g_atth (fp16 only)
// ============================================================================
__global__ void __launch_bounds__(256, 2) gemm3_kernel() {
    const int b = blockIdx.x;
    gemm16_tile<true, true>(MDIM, SPATIAL, g_xh, g_mnh, nullptr, g_atth,
                            g_invnorm, (b >> 2) * 128, (b & 3) * 128);
}

// ============================================================================
// softmax + shrink + L1 renorm from fp16 logits; writes f32 att to d_out and
// fp16 att in place. Warp per row.
// ============================================================================
__global__ __launch_bounds__(256) void softmax_shrink_kernel(float* __restrict__ att) {
    const int row  = blockIdx.x * 8 + (threadIdx.x >> 5);
    const int lane = threadIdx.x & 31;
    uint2*  ph = (uint2*)(g_atth + (size_t)row * MDIM);
    float4* pf = (float4*)(att + (size_t)row * MDIM);
    float f[16];
#pragma unroll
    for (int i = 0; i < 4; i++) {
        uint2 u = ph[lane + 32 * i];
        __half2 h0 = *reinterpret_cast<__half2*>(&u.x);
        __half2 h1 = *reinterpret_cast<__half2*>(&u.y);
        float2 a = __half22float2(h0), bb = __half22float2(h1);
        f[4 * i + 0] = a.x;  f[4 * i + 1] = a.y;
        f[4 * i + 2] = bb.x; f[4 * i + 3] = bb.y;
    }
    float m = -INFINITY;
#pragma unroll
    for (int i = 0; i < 16; i++) m = fmaxf(m, f[i]);
    m = warp_max(m);
    float s = 0.0f;
#pragma unroll
    for (int i = 0; i < 16; i++) { f[i] = expf(f[i] - m); s += f[i]; }
    s = warp_sum(s);
    const float inv = 1.0f / s;
    float t = 0.0f;
#pragma unroll
    for (int i = 0; i < 16; i++) {
        f[i] = fmaxf(f[i] * inv - 0.0025f, 0.0f);
        t += f[i];
    }
    t = warp_sum(t);
    const float inv2 = 1.0f / fmaxf(t, 1e-12f);
#pragma unroll
    for (int i = 0; i < 4; i++) {
        float v0 = f[4 * i + 0] * inv2, v1 = f[4 * i + 1] * inv2;
        float v2 = f[4 * i + 2] * inv2, v3 = f[4 * i + 3] * inv2;
        pf[lane + 32 * i] = make_float4(v0, v1, v2, v3);
        ph[lane + 32 * i] = make_uint2(pack_half2(v0, v1), pack_half2(v2, v3));
    }
}

// ============================================================================
// K4: tail blocks (chanmean+bcast, 128) first, then GEMM4 (1024 blocks)
// ============================================================================
__global__ void __launch_bounds__(256, 2) k4_gemm4_tail(
    float* __restrict__ outp, float* __restrict__ attsp)
{
    const int b = blockIdx.x;
    if (b >= 128) {
        const int g = b - 128;
        gemm16_tile<false, false>(SPATIAL, MDIM, g_atth, g_mnTh, outp, nullptr,
                                  nullptr, (g >> 3) * 128, (g & 7) * 128);
        return;
    }
    extern __shared__ float sf[];
    const int n  = b >> 2;
    const int mg = b & 3;
    const int t  = threadIdx.x;
    const int m  = t & 127;
    const int ch = t >> 7;
    const __half* base = g_atth + ((size_t)(n * 512 + ch * 256)) * MDIM + mg * 128 + m;
    float s = 0.0f;
#pragma unroll 4
    for (int c = 0; c < 256; c++) s += __half2float(base[(size_t)c * MDIM]);
    sf[t] = s;
    __syncthreads();
    if (t < 128) sf[256 + t] = (sf[t] + sf[t + 128]) * (1.0f / 512.0f);
    __syncthreads();
    float* dst0 = attsp + ((size_t)(n * MDIM + mg * 128)) * SPATIAL;
    for (int m2 = 0; m2 < 128; m2++) {
        const float v = sf[256 + m2];
        ((float4*)(dst0 + (size_t)m2 * SPATIAL))[t] = make_float4(v, v, v, v);
    }
}

// ============================================================================
extern "C" void kernel_launch(void* const* d_in, const int* in_sizes, int n_in,
                              void* d_out, int out_size) {
    (void)in_sizes; (void)n_in; (void)out_size;
    const float* x      = (const float*)d_in[0];
    const float* memory = (const float*)d_in[1];
    const float* w1     = (const float*)d_in[2];
    const float* b1     = (const float*)d_in[3];
    const float* w2     = (const float*)d_in[4];
    const float* b2     = (const float*)d_in[5];

    float* out = (float*)d_out;
    float* out_output  = out + OFF_OUTPUT;
    float* out_attsp   = out + OFF_ATTSP;
    float* out_inflat  = out + OFF_INFLAT;
    float* out_memnorm = out + OFF_MEMNORM;
    float* out_att     = out + OFF_ATT;

    cudaFuncSetAttribute((const void*)k1_mlp1_input,
                         cudaFuncAttributeMaxDynamicSharedMemorySize, GEMM_SMEM_BYTES);
    cudaFuncSetAttribute((const void*)k2_mlp2_input,
                         cudaFuncAttributeMaxDynamicSharedMemorySize, GEMM_SMEM_BYTES);
    cudaFuncSetAttribute((const void*)gemm3_kernel,
                         cudaFuncAttributeMaxDynamicSharedMemorySize, HGEMM_SMEM_BYTES);
    cudaFuncSetAttribute((const void*)k4_gemm4_tail,
                         cudaFuncAttributeMaxDynamicSharedMemorySize, HGEMM_SMEM_BYTES);

    // L1: MLP layer 1 || input processing (rows 0..K1_ROWS-1)
    k1_mlp1_input<<<148, 256, GEMM_SMEM_BYTES>>>(memory, w1, b1, x, out_inflat);
    // L2: MLP layer 2 || input processing (rows K1_ROWS..16383)
    k2_mlp2_input<<<148, 256, GEMM_SMEM_BYTES>>>(w2, b2, x, out_inflat);
    // L3: memory_norm (f32 + fp16 + fp16-transposed)
    rownorm_t_kernel<<<MDIM, 256>>>(out_memnorm);
    // L4: addressing logits (fp16) -> g_atth
    gemm3_kernel<<<512, 256, HGEMM_SMEM_BYTES>>>();
    // L5: softmax + shrink + renorm: fp16 logits -> f32 att (d_out) + fp16 att
    softmax_shrink_kernel<<<R_ROWS / 8, 256>>>(out_att);
    // L6: output GEMM + fused channel-mean/broadcast
    k4_gemm4_tail<<<1152, 256, HGEMM_SMEM_BYTES>>>(out_output, out_attsp);
}

// round 14
// speedup vs baseline: 1.6021x; 1.2998x over previous
#include <cuda_runtime.h>
#include <cuda_fp16.h>
#include <cstdint>
#include <math.h>

// Problem constants
#define R_ROWS  16384   // N*C
#define SPATIAL 1024    // H*W
#define MDIM    512     // mem_dim
#define HIDDIM  512     // spatial/2

// d_out section offsets (floats)
#define OFF_OUTPUT   ((size_t)0)
#define OFF_ATTSP    ((size_t)16777216)
#define OFF_INFLAT   ((size_t)33554432)
#define OFF_MEMNORM  ((size_t)50331648)
#define OFF_ATT      ((size_t)50855936)

// Device scratch (allocation-free)
__device__ float  g_h[MDIM * HIDDIM];
__device__ float  g_memproc[MDIM * SPATIAL];
__device__ float  g_invnorm[R_ROWS];
__device__ __half g_xh[(size_t)R_ROWS * SPATIAL];    // fp16 x
__device__ __half g_mnh[MDIM * SPATIAL];             // fp16 memory_norm
__device__ __half g_mnTh[SPATIAL * MDIM];            // fp16 memory_norm^T
__device__ __half g_atth[(size_t)R_ROWS * MDIM];     // fp16 logits -> fp16 att
__device__ int    g_bflag[R_ROWS / 128];             // per-128-row survivor flags

// ============================================================================
// mma.sync helpers (sm_80+ — base compute_103 target safe)
// ============================================================================
__device__ __forceinline__ void mma8_tf32(float* c, uint32_t a0, uint32_t a1,
                                          uint32_t a2, uint32_t a3,
                                          uint32_t b0, uint32_t b1) {
    asm volatile(
        "mma.sync.aligned.m16n8k8.row.col.f32.tf32.tf32.f32 "
        "{%0,%1,%2,%3}, {%4,%5,%6,%7}, {%8,%9}, {%0,%1,%2,%3};"
        : "+f"(c[0]), "+f"(c[1]), "+f"(c[2]), "+f"(c[3])
        : "r"(a0), "r"(a1), "r"(a2), "r"(a3), "r"(b0), "r"(b1));
}

__device__ __forceinline__ void mma16_f16(float* c, uint32_t a0, uint32_t a1,
                                          uint32_t a2, uint32_t a3,
                                          uint32_t b0, uint32_t b1) {
    asm volatile(
        "mma.sync.aligned.m16n8k16.row.col.f32.f16.f16.f32 "
        "{%0,%1,%2,%3}, {%4,%5,%6,%7}, {%8,%9}, {%0,%1,%2,%3};"
        : "+f"(c[0]), "+f"(c[1]), "+f"(c[2]), "+f"(c[3])
        : "r"(a0), "r"(a1), "r"(a2), "r"(a3), "r"(b0), "r"(b1));
}

__device__ __forceinline__ void ldmx4(uint32_t& r0, uint32_t& r1,
                                      uint32_t& r2, uint32_t& r3, uint32_t addr) {
    asm volatile("ldmatrix.sync.aligned.m8n8.x4.shared.b16 {%0,%1,%2,%3}, [%4];"
                 : "=r"(r0), "=r"(r1), "=r"(r2), "=r"(r3) : "r"(addr));
}

__device__ __forceinline__ uint32_t tf32_hi(float x) {
    uint32_t h;
    asm("cvt.rna.tf32.f32 %0, %1;" : "=r"(h) : "f"(x));
    return h;
}

__device__ __forceinline__ void cp16(uint32_t dst, const void* src) {
    asm volatile("cp.async.cg.shared.global [%0], [%1], 16;" :: "r"(dst), "l"(src));
}

__device__ __forceinline__ uint32_t pack_half2(float a, float b) {
    __half2 h = __floats2half2_rn(a, b);
    return *reinterpret_cast<uint32_t*>(&h);
}

__device__ __forceinline__ float warp_sum(float v) {
#pragma unroll
    for (int o = 16; o > 0; o >>= 1) v += __shfl_xor_sync(0xffffffffu, v, o);
    return v;
}
__device__ __forceinline__ float warp_max(float v) {
#pragma unroll
    for (int o = 16; o > 0; o >>= 1) v = fmaxf(v, __shfl_xor_sync(0xffffffffu, v, o));
    return v;
}

// ============================================================================
// tf32 NT GEMM tile (device fn) — precision-critical MLP path.
// CTA tile 128x128xBK32, 8 warps, 3-stage cp.async.
// ============================================================================
#define SSTRIDE 36
#define TILEF   (128 * SSTRIDE)
#define STAGEF  (2 * TILEF)
#define GEMM_SMEM_BYTES (3 * STAGEF * 4)

__device__ void mlp_tile(
    int Ntot, int K,
    const float* __restrict__ A, const float* __restrict__ B,
    float* __restrict__ C, const float* __restrict__ bias,
    int bm, int bn)
{
    extern __shared__ float smf[];
    const uint32_t sbase = (uint32_t)__cvta_generic_to_shared(smf);
    const int tid  = threadIdx.x;
    const int wid  = tid >> 5;
    const int lane = tid & 31;
    const int wm   = wid & 1;
    const int wn   = wid >> 1;
    const int tr   = lane >> 2;
    const int tc   = lane & 3;

    const float* At = A + (size_t)bm * K;
    const float* Bt = B + (size_t)bn * K;
    const int nk = K >> 5;

    auto load_stage = [&](int st, int kc) {
        const uint32_t so = sbase + (uint32_t)(st * STAGEF * 4);
#pragma unroll
        for (int i = 0; i < 4; i++) {
            int u = tid + i * 256;
            int row = u >> 3;
            int seg = (u & 7) * 4;
            cp16(so + (uint32_t)((row * SSTRIDE + seg) * 4),
                 At + (size_t)row * K + kc * 32 + seg);
            cp16(so + (uint32_t)((TILEF + row * SSTRIDE + seg) * 4),
                 Bt + (size_t)row * K + kc * 32 + seg);
        }
        asm volatile("cp.async.commit_group;" ::: "memory");
    };

    float c[4][4][4];
#pragma unroll
    for (int mf = 0; mf < 4; mf++)
#pragma unroll
        for (int nf = 0; nf < 4; nf++)
#pragma unroll
            for (int q = 0; q < 4; q++) c[mf][nf][q] = 0.0f;

    load_stage(0, 0);
    load_stage(1, 1);

    for (int s = 0; s < nk; ++s) {
        if (s + 1 < nk) asm volatile("cp.async.wait_group 1;" ::: "memory");
        else            asm volatile("cp.async.wait_group 0;" ::: "memory");
        __syncthreads();
        if (s + 2 < nk) load_stage((s + 2) % 3, s + 2);

        const float* As = smf + (s % 3) * STAGEF;
        const float* Bs = As + TILEF;

#pragma unroll
        for (int kk = 0; kk < 4; kk++) {
            const int kb = kk * 8;
            uint32_t ah[4][4], bh[4][2];
#pragma unroll
            for (int mf = 0; mf < 4; mf++) {
                const int r0 = wm * 64 + mf * 16 + tr;
                ah[mf][0] = tf32_hi(As[r0 * SSTRIDE + kb + tc]);
                ah[mf][1] = tf32_hi(As[(r0 + 8) * SSTRIDE + kb + tc]);
                ah[mf][2] = tf32_hi(As[r0 * SSTRIDE + kb + tc + 4]);
                ah[mf][3] = tf32_hi(As[(r0 + 8) * SSTRIDE + kb + tc + 4]);
            }
#pragma unroll
            for (int nf = 0; nf < 4; nf++) {
                const int n0 = wn * 32 + nf * 8 + tr;
                bh[nf][0] = tf32_hi(Bs[n0 * SSTRIDE + kb + tc]);
                bh[nf][1] = tf32_hi(Bs[n0 * SSTRIDE + kb + tc + 4]);
            }
#pragma unroll
            for (int mf = 0; mf < 4; mf++)
#pragma unroll
                for (int nf = 0; nf < 4; nf++)
                    mma8_tf32(c[mf][nf], ah[mf][0], ah[mf][1], ah[mf][2], ah[mf][3],
                              bh[nf][0], bh[nf][1]);
        }
    }

#pragma unroll
    for (int mf = 0; mf < 4; mf++) {
        const int r0g = bm + wm * 64 + mf * 16 + tr;
#pragma unroll
        for (int nf = 0; nf < 4; nf++) {
            const int cg = bn + wn * 32 + nf * 8 + 2 * tc;
            float bb0 = bias[cg], bb1 = bias[cg + 1];
            float v0 = fmaxf(c[mf][nf][0] + bb0, 0.0f);
            float v1 = fmaxf(c[mf][nf][1] + bb1, 0.0f);
            float v2 = fmaxf(c[mf][nf][2] + bb0, 0.0f);
            float v3 = fmaxf(c[mf][nf][3] + bb1, 0.0f);
            *(float2*)&C[(size_t)r0g * Ntot + cg]       = make_float2(v0, v1);
            *(float2*)&C[(size_t)(r0g + 8) * Ntot + cg] = make_float2(v2, v3);
        }
    }
}

// ============================================================================
// fp16 NT GEMM tile: 4-stage pipeline, 2 CTAs/SM.
// FP16OUT=false: f32 store to C. FP16OUT=true: fp16 (rowscaled) store to Dh.
// ============================================================================
#define SSW      20
#define HTILEW   (128 * SSW)
#define HSTAGEW  (2 * HTILEW)
#define HGEMM_SMEM_BYTES (4 * HSTAGEW * 4)   // 81920 B

template <bool ROWSCALE, bool FP16OUT>
__device__ void gemm16_tile(
    int Ntot, int K,
    const __half* __restrict__ A, const __half* __restrict__ B,
    float* __restrict__ C, __half* __restrict__ Dh,
    const float* __restrict__ rowscale,
    int bm, int bn)
{
    extern __shared__ uint32_t smw[];
    const uint32_t sbase = (uint32_t)__cvta_generic_to_shared(smw);
    const int tid  = threadIdx.x;
    const int wid  = tid >> 5;
    const int lane = tid & 31;
    const int wm   = wid & 1;
    const int wn   = wid >> 1;
    const int tr   = lane >> 2;
    const int tc   = lane & 3;

    const __half* At = A + (size_t)bm * K;
    const __half* Bt = B + (size_t)bn * K;
    const int nk = K >> 5;

    const int q = lane >> 3;
    const int rsub = lane & 7;
    const int arow = wm * 64 + rsub + (q & 1) * 8;
    const int acolw = (q >> 1) * 4;
    const int brow = wn * 32 + rsub + (q >> 1) * 8;
    const int bcolw = (q & 1) * 4;

    auto load_stage = [&](int st, int kc) {
        const uint32_t so = sbase + (uint32_t)(st * HSTAGEW * 4);
#pragma unroll
        for (int i = 0; i < 2; i++) {
            int u = tid + i * 256;
            int row = u >> 2;
            int seg = (u & 3) * 4;
            cp16(so + (uint32_t)((row * SSW + seg) * 4),
                 At + (size_t)row * K + kc * 32 + seg * 2);
            cp16(so + (uint32_t)((HTILEW + row * SSW + seg) * 4),
                 Bt + (size_t)row * K + kc * 32 + seg * 2);
        }
        asm volatile("cp.async.commit_group;" ::: "memory");
    };

    float c[4][4][4];
#pragma unroll
    for (int mf = 0; mf < 4; mf++)
#pragma unroll
        for (int nf = 0; nf < 4; nf++)
#pragma unroll
            for (int qq = 0; qq < 4; qq++) c[mf][nf][qq] = 0.0f;

    load_stage(0, 0);
    load_stage(1, 1);
    load_stage(2, 2);

    for (int s = 0; s < nk; ++s) {
        if (s + 2 < nk)      asm volatile("cp.async.wait_group 2;" ::: "memory");
        else if (s + 1 < nk) asm volatile("cp.async.wait_group 1;" ::: "memory");
        else                 asm volatile("cp.async.wait_group 0;" ::: "memory");
        __syncthreads();
        if (s + 3 < nk) load_stage((s + 3) & 3, s + 3);

        const uint32_t stage = sbase + (uint32_t)((s & 3) * HSTAGEW * 4);
        const uint32_t aAddr0 = stage + (uint32_t)((arow * SSW + acolw) * 4);
        const uint32_t bAddr0 = stage + (uint32_t)((HTILEW + brow * SSW + bcolw) * 4);

#pragma unroll
        for (int kk = 0; kk < 2; kk++) {
            const uint32_t kboff = (uint32_t)(kk * 8 * 4);
            uint32_t a[4][4], b[4][2];
#pragma unroll
            for (int mf = 0; mf < 4; mf++)
                ldmx4(a[mf][0], a[mf][1], a[mf][2], a[mf][3],
                      aAddr0 + kboff + (uint32_t)(mf * 16 * SSW * 4));
#pragma unroll
            for (int nf2 = 0; nf2 < 2; nf2++)
                ldmx4(b[2 * nf2][0], b[2 * nf2][1], b[2 * nf2 + 1][0], b[2 * nf2 + 1][1],
                      bAddr0 + kboff + (uint32_t)(nf2 * 16 * SSW * 4));
#pragma unroll
            for (int mf = 0; mf < 4; mf++)
#pragma unroll
                for (int nf = 0; nf < 4; nf++)
                    mma16_f16(c[mf][nf], a[mf][0], a[mf][1], a[mf][2], a[mf][3],
                              b[nf][0], b[nf][1]);
        }
    }

#pragma unroll
    for (int mf = 0; mf < 4; mf++) {
        const int r0g = bm + wm * 64 + mf * 16 + tr;
        const float rs0 = ROWSCALE ? rowscale[r0g] : 1.0f;
        const float rs1 = ROWSCALE ? rowscale[r0g + 8] : 1.0f;
#pragma unroll
        for (int nf = 0; nf < 4; nf++) {
            const int cg = bn + wn * 32 + nf * 8 + 2 * tc;
            float v0 = c[mf][nf][0], v1 = c[mf][nf][1];
            float v2 = c[mf][nf][2], v3 = c[mf][nf][3];
            if (ROWSCALE) { v0 *= rs0; v1 *= rs0; v2 *= rs1; v3 *= rs1; }
            if (FP16OUT) {
                *(uint32_t*)&Dh[(size_t)r0g * Ntot + cg]       = pack_half2(v0, v1);
                *(uint32_t*)&Dh[(size_t)(r0g + 8) * Ntot + cg] = pack_half2(v2, v3);
            } else {
                *(float2*)&C[(size_t)r0g * Ntot + cg]       = make_float2(v0, v1);
                *(float2*)&C[(size_t)(r0g + 8) * Ntot + cg] = make_float2(v2, v3);
            }
        }
    }
}

// ============================================================================
// Fused input processing: copy x -> input_flat, fp16(x) -> g_xh, invnorm.
// ============================================================================
__device__ void input_rows(const float* __restrict__ x, float* __restrict__ inflat,
                           int gwarp, int nwarps, int base, int count) {
    const int lane = threadIdx.x & 31;
    for (int row = base + gwarp; row < base + count; row += nwarps) {
        const float4* p = (const float4*)(x + (size_t)row * SPATIAL);
        float4* of = (float4*)(inflat + (size_t)row * SPATIAL);
        uint2*  xo = (uint2*)(g_xh + (size_t)row * SPATIAL);
        float s = 0.0f;
#pragma unroll
        for (int i = 0; i < 8; i++) {
            float4 v = p[lane + 32 * i];
            s += v.x * v.x + v.y * v.y + v.z * v.z + v.w * v.w;
            of[lane + 32 * i] = v;
            xo[lane + 32 * i] = make_uint2(pack_half2(v.x, v.y), pack_half2(v.z, v.w));
        }
        s = warp_sum(s);
        if (lane == 0) g_invnorm[row] = 1.0f / fmaxf(sqrtf(s), 1e-12f);
    }
}

// K1: MLP1 (16 CTAs) + input rows 0..8191 (132 CTAs)
__global__ void __launch_bounds__(256, 1) k1_mlp1_input(
    const float* __restrict__ memory, const float* __restrict__ w1,
    const float* __restrict__ b1, const float* __restrict__ x,
    float* __restrict__ inflat)
{
    const int b = blockIdx.x;
    if (b < 16) {
        mlp_tile(HIDDIM, SPATIAL, memory, w1, g_h, b1, (b >> 2) * 128, (b & 3) * 128);
    } else {
        const int gwarp = (b - 16) * 8 + (threadIdx.x >> 5);
        input_rows(x, inflat, gwarp, 132 * 8, 0, 8192);
    }
}

// K2: MLP2 (32 CTAs) + input rows 8192..16383 (116 CTAs)
__global__ void __launch_bounds__(256, 1) k2_mlp2_input(
    const float* __restrict__ w2, const float* __restrict__ b2,
    const float* __restrict__ x, float* __restrict__ inflat)
{
    const int b = blockIdx.x;
    if (b < 32) {
        mlp_tile(SPATIAL, HIDDIM, g_h, w2, g_memproc, b2, (b >> 3) * 128, (b & 7) * 128);
    } else {
        const int gwarp = (b - 32) * 8 + (threadIdx.x >> 5);
        input_rows(x, inflat, gwarp, 116 * 8, 8192, 8192);
    }
}

// ============================================================================
// rownorm + fp16 + transposed fp16 in one pass. Block per row.
// ============================================================================
__global__ __launch_bounds__(256) void rownorm_t_kernel(float* __restrict__ dst) {
    __shared__ float sm[8];
    const int row  = blockIdx.x;
    const int tid  = threadIdx.x;
    const int lane = tid & 31;
    const int w    = tid >> 5;
    const float4* p = (const float4*)(g_memproc + (size_t)row * SPATIAL);
    float4 v = p[tid];
    float s = v.x * v.x + v.y * v.y + v.z * v.z + v.w * v.w;
    s = warp_sum(s);
    if (lane == 0) sm[w] = s;
    __syncthreads();
    float tot = 0.0f;
#pragma unroll
    for (int i = 0; i < 8; i++) tot += sm[i];
    const float sc = 1.0f / fmaxf(sqrtf(tot), 1e-12f);
    float4 o = make_float4(v.x * sc, v.y * sc, v.z * sc, v.w * sc);
    ((float4*)(dst + (size_t)row * SPATIAL))[tid] = o;
    ((uint2*)(g_mnh + (size_t)row * SPATIAL))[tid] =
        make_uint2(pack_half2(o.x, o.y), pack_half2(o.z, o.w));
    g_mnTh[(size_t)(4 * tid + 0) * MDIM + row] = __float2half_rn(o.x);
    g_mnTh[(size_t)(4 * tid + 1) * MDIM + row] = __float2half_rn(o.y);
    g_mnTh[(size_t)(4 * tid + 2) * MDIM + row] = __float2half_rn(o.z);
    g_mnTh[(size_t)(4 * tid + 3) * MDIM + row] = __float2half_rn(o.w);
}

// ============================================================================
// GEMM3: fp16 rowscaled logits -> g_atth. Also zeroes the survivor flags
// (one per 128-row block) so the following softmax launch can OR into them.
// ============================================================================
__global__ void __launch_bounds__(256, 2) gemm3_kernel() {
    const int b = blockIdx.x;
    if ((b & 3) == 0 && threadIdx.x == 0) g_bflag[b >> 2] = 0;
    gemm16_tile<true, true>(MDIM, SPATIAL, g_xh, g_mnh, nullptr, g_atth,
                            g_invnorm, (b >> 2) * 128, (b & 3) * 128);
}

// ============================================================================
// softmax + shrink + L1 renorm from fp16 logits; writes f32 att to d_out and
// fp16 att in place. Flags row-blocks that contain any survivor.
// ============================================================================
__global__ __launch_bounds__(256) void softmax_shrink_kernel(float* __restrict__ att) {
    const int row  = blockIdx.x * 8 + (threadIdx.x >> 5);
    const int lane = threadIdx.x & 31;
    uint2*  ph = (uint2*)(g_atth + (size_t)row * MDIM);
    float4* pf = (float4*)(att + (size_t)row * MDIM);
    float f[16];
#pragma unroll
    for (int i = 0; i < 4; i++) {
        uint2 u = ph[lane + 32 * i];
        __half2 h0 = *reinterpret_cast<__half2*>(&u.x);
        __half2 h1 = *reinterpret_cast<__half2*>(&u.y);
        float2 a = __half22float2(h0), bb = __half22float2(h1);
        f[4 * i + 0] = a.x;  f[4 * i + 1] = a.y;
        f[4 * i + 2] = bb.x; f[4 * i + 3] = bb.y;
    }
    float m = -INFINITY;
#pragma unroll
    for (int i = 0; i < 16; i++) m = fmaxf(m, f[i]);
    m = warp_max(m);
    float s = 0.0f;
#pragma unroll
    for (int i = 0; i < 16; i++) { f[i] = expf(f[i] - m); s += f[i]; }
    s = warp_sum(s);
    const float inv = 1.0f / s;
    float t = 0.0f;
#pragma unroll
    for (int i = 0; i < 16; i++) {
        f[i] = fmaxf(f[i] * inv - 0.0025f, 0.0f);
        t += f[i];
    }
    t = warp_sum(t);
    if (lane == 0 && t > 0.0f) atomicOr(&g_bflag[row >> 7], 1);
    const float inv2 = 1.0f / fmaxf(t, 1e-12f);
#pragma unroll
    for (int i = 0; i < 4; i++) {
        float v0 = f[4 * i + 0] * inv2, v1 = f[4 * i + 1] * inv2;
        float v2 = f[4 * i + 2] * inv2, v3 = f[4 * i + 3] * inv2;
        pf[lane + 32 * i] = make_float4(v0, v1, v2, v3);
        ph[lane + 32 * i] = make_uint2(pack_half2(v0, v1), pack_half2(v2, v3));
    }
}

// ============================================================================
// K4: tail blocks (chanmean+bcast, 128) first, then GEMM4 (1024 blocks).
// Sparsity-aware: row-blocks with no survivors produce zero tiles directly.
// ============================================================================
__global__ void __launch_bounds__(256, 2) k4_gemm4_tail(
    float* __restrict__ outp, float* __restrict__ attsp)
{
    const int b = blockIdx.x;
    const int t = threadIdx.x;
    if (b >= 128) {
        const int g = b - 128;
        const int rb = g >> 3;                  // 128-row block index
        const int bm = rb * 128;
        const int bn = (g & 7) * 128;
        if (g_bflag[rb] == 0) {
            // att rows all zero -> output tile is zero. Pure store.
            float4 z = make_float4(0.f, 0.f, 0.f, 0.f);
#pragma unroll
            for (int i = 0; i < 16; i++) {
                int u = t + i * 256;            // 0..4095 float4s
                int r = u >> 5;                 // 0..127
                int c4 = u & 31;                // 0..31
                ((float4*)&outp[(size_t)(bm + r) * SPATIAL + bn])[c4] = z;
            }
            return;
        }
        gemm16_tile<false, false>(SPATIAL, MDIM, g_atth, g_mnTh, outp, nullptr,
                                  nullptr, bm, bn);
        return;
    }
    // tail: channel-mean over 512 channels + spatial broadcast
    const int n  = b >> 2;
    const int mg = b & 3;
    // att rows for batch n are row-blocks 4n..4n+3
    const int any = g_bflag[4 * n] | g_bflag[4 * n + 1] |
                    g_bflag[4 * n + 2] | g_bflag[4 * n + 3];
    float* dst0 = attsp + ((size_t)(n * MDIM + mg * 128)) * SPATIAL;
    if (any == 0) {
        float4 z = make_float4(0.f, 0.f, 0.f, 0.f);
        for (int m2 = 0; m2 < 128; m2++)
            ((float4*)(dst0 + (size_t)m2 * SPATIAL))[t] = z;
        return;
    }
    extern __shared__ float sf[];
    const int m  = t & 127;
    const int ch = t >> 7;
    const __half* base = g_atth + ((size_t)(n * 512 + ch * 256)) * MDIM + mg * 128 + m;
    float s = 0.0f;
#pragma unroll 4
    for (int c = 0; c < 256; c++) s += __half2float(base[(size_t)c * MDIM]);
    sf[t] = s;
    __syncthreads();
    if (t < 128) sf[256 + t] = (sf[t] + sf[t + 128]) * (1.0f / 512.0f);
    __syncthreads();
    for (int m2 = 0; m2 < 128; m2++) {
        const float v = sf[256 + m2];
        ((float4*)(dst0 + (size_t)m2 * SPATIAL))[t] = make_float4(v, v, v, v);
    }
}

// ============================================================================
extern "C" void kernel_launch(void* const* d_in, const int* in_sizes, int n_in,
                              void* d_out, int out_size) {
    (void)in_sizes; (void)n_in; (void)out_size;
    const float* x      = (const float*)d_in[0];
    const float* memory = (const float*)d_in[1];
    const float* w1     = (const float*)d_in[2];
    const float* b1     = (const float*)d_in[3];
    const float* w2     = (const float*)d_in[4];
    const float* b2     = (const float*)d_in[5];

    float* out = (float*)d_out;
    float* out_output  = out + OFF_OUTPUT;
    float* out_attsp   = out + OFF_ATTSP;
    float* out_inflat  = out + OFF_INFLAT;
    float* out_memnorm = out + OFF_MEMNORM;
    float* out_att     = out + OFF_ATT;

    cudaFuncSetAttribute((const void*)k1_mlp1_input,
                         cudaFuncAttributeMaxDynamicSharedMemorySize, GEMM_SMEM_BYTES);
    cudaFuncSetAttribute((const void*)k2_mlp2_input,
                         cudaFuncAttributeMaxDynamicSharedMemorySize, GEMM_SMEM_BYTES);
    cudaFuncSetAttribute((const void*)gemm3_kernel,
                         cudaFuncAttributeMaxDynamicSharedMemorySize, HGEMM_SMEM_BYTES);
    cudaFuncSetAttribute((const void*)k4_gemm4_tail,
                         cudaFuncAttributeMaxDynamicSharedMemorySize, HGEMM_SMEM_BYTES);

    // L1: MLP layer 1 || input processing (rows 0..8191)
    k1_mlp1_input<<<148, 256, GEMM_SMEM_BYTES>>>(memory, w1, b1, x, out_inflat);
    // L2: MLP layer 2 || input processing (rows 8192..16383)
    k2_mlp2_input<<<148, 256, GEMM_SMEM_BYTES>>>(w2, b2, x, out_inflat);
    // L3: memory_norm (f32 + fp16 + fp16-transposed)
    rownorm_t_kernel<<<MDIM, 256>>>(out_memnorm);
    // L4: addressing logits (fp16) -> g_atth (+ flag reset)
    gemm3_kernel<<<512, 256, HGEMM_SMEM_BYTES>>>();
    // L5: softmax + shrink + renorm (+ survivor flags)
    softmax_shrink_kernel<<<R_ROWS / 8, 256>>>(out_att);
    // L6: output GEMM (sparsity-aware) + fused channel-mean/broadcast
    k4_gemm4_tail<<<1152, 256, HGEMM_SMEM_BYTES>>>(out_output, out_attsp);
}